// round 4
// baseline (speedup 1.0000x reference)
#include <cuda_runtime.h>

// Loss_Antonymy: out = sum_i relu(1 + sign_i * tanh(||A1_i - S2_i||_2)),
// sign_i = -1 if labels[i]==2 else +1.
// N = 1048576, D = 64. Inputs: S2_out [N*64] f32, A1_out [N*64] f32, labels [N] int32.
// Output: 1 float.
//
// R4: unroll x4 (8 rows per warp iteration), 8 front-batched float4 loads
// (per-thread MLP = 8) to test cadence-limited vs LTS-capped.

#define D 64

__global__ void zero_out_kernel(float* out) {
    out[0] = 0.0f;
}

__global__ __launch_bounds__(256)
void loss_antonymy_kernel(const float* __restrict__ S2,
                          const float* __restrict__ A1,
                          const int* __restrict__ labels,
                          float* __restrict__ out,
                          int nrows)
{
    const int lane  = threadIdx.x & 31;
    const int half  = lane >> 4;        // 0 or 1: which row within a pair
    const int sub   = lane & 15;        // 16 float4 = 64 floats of one row
    const int gwarp = (blockIdx.x * blockDim.x + threadIdx.x) >> 5;
    const int nwarp = (gridDim.x * blockDim.x) >> 5;
    const int ngroups = nrows >> 3;     // 8 rows per warp iteration

    float acc = 0.0f;

    for (int grp = gwarp; grp < ngroups; grp += nwarp) {
        const long long rowb = (long long)grp * 8 + half;

        // front-batch all 8 independent 16B loads (MLP=8 per thread)
        float4 av0 = __ldg(reinterpret_cast<const float4*>(A1 + (rowb + 0) * D) + sub);
        float4 sv0 = __ldg(reinterpret_cast<const float4*>(S2 + (rowb + 0) * D) + sub);
        float4 av1 = __ldg(reinterpret_cast<const float4*>(A1 + (rowb + 2) * D) + sub);
        float4 sv1 = __ldg(reinterpret_cast<const float4*>(S2 + (rowb + 2) * D) + sub);
        float4 av2 = __ldg(reinterpret_cast<const float4*>(A1 + (rowb + 4) * D) + sub);
        float4 sv2 = __ldg(reinterpret_cast<const float4*>(S2 + (rowb + 4) * D) + sub);
        float4 av3 = __ldg(reinterpret_cast<const float4*>(A1 + (rowb + 6) * D) + sub);
        float4 sv3 = __ldg(reinterpret_cast<const float4*>(S2 + (rowb + 6) * D) + sub);

        float dx, dy, dz, dw;
        dx = av0.x - sv0.x; dy = av0.y - sv0.y; dz = av0.z - sv0.z; dw = av0.w - sv0.w;
        float ss0 = dx*dx + dy*dy + dz*dz + dw*dw;
        dx = av1.x - sv1.x; dy = av1.y - sv1.y; dz = av1.z - sv1.z; dw = av1.w - sv1.w;
        float ss1 = dx*dx + dy*dy + dz*dz + dw*dw;
        dx = av2.x - sv2.x; dy = av2.y - sv2.y; dz = av2.z - sv2.z; dw = av2.w - sv2.w;
        float ss2 = dx*dx + dy*dy + dz*dz + dw*dw;
        dx = av3.x - sv3.x; dy = av3.y - sv3.y; dz = av3.z - sv3.z; dw = av3.w - sv3.w;
        float ss3 = dx*dx + dy*dy + dz*dz + dw*dw;

        // reduce each across the 16 lanes of this half-warp
        #pragma unroll
        for (int o = 8; o > 0; o >>= 1) {
            ss0 += __shfl_xor_sync(0xffffffffu, ss0, o);
            ss1 += __shfl_xor_sync(0xffffffffu, ss1, o);
            ss2 += __shfl_xor_sync(0xffffffffu, ss2, o);
            ss3 += __shfl_xor_sync(0xffffffffu, ss3, o);
        }

        if (sub == 0) {
            float sg0 = (labels[rowb + 0] == 2) ? -1.0f : 1.0f;
            float sg1 = (labels[rowb + 2] == 2) ? -1.0f : 1.0f;
            float sg2 = (labels[rowb + 4] == 2) ? -1.0f : 1.0f;
            float sg3 = (labels[rowb + 6] == 2) ? -1.0f : 1.0f;
            acc += fmaxf(0.0f, fmaf(sg0, tanhf(sqrtf(ss0)), 1.0f));
            acc += fmaxf(0.0f, fmaf(sg1, tanhf(sqrtf(ss1)), 1.0f));
            acc += fmaxf(0.0f, fmaf(sg2, tanhf(sqrtf(ss2)), 1.0f));
            acc += fmaxf(0.0f, fmaf(sg3, tanhf(sqrtf(ss3)), 1.0f));
        }
    }

    // block reduction: intra-warp, then across warps via shared, one atomic per block
    #pragma unroll
    for (int o = 16; o > 0; o >>= 1)
        acc += __shfl_xor_sync(0xffffffffu, acc, o);

    __shared__ float wsum[8];   // 256 threads -> 8 warps
    const int wid = threadIdx.x >> 5;
    if (lane == 0) wsum[wid] = acc;
    __syncthreads();

    if (wid == 0) {
        float v = (lane < (blockDim.x >> 5)) ? wsum[lane] : 0.0f;
        #pragma unroll
        for (int o = 4; o > 0; o >>= 1)
            v += __shfl_xor_sync(0xffffffffu, v, o);
        if (lane == 0)
            atomicAdd(out, v);
    }
}

extern "C" void kernel_launch(void* const* d_in, const int* in_sizes, int n_in,
                              void* d_out, int out_size)
{
    const float* S2     = (const float*)d_in[0];
    const float* A1     = (const float*)d_in[1];
    const int*   labels = (const int*)d_in[2];
    float*       out    = (float*)d_out;

    const int nrows = in_sizes[2];   // labels element count = N

    zero_out_kernel<<<1, 1>>>(out);

    const int blocks = 148 * 8;
    loss_antonymy_kernel<<<blocks, 256>>>(S2, A1, labels, out, nrows);
}

// round 5
// speedup vs baseline: 1.1089x; 1.1089x over previous
#include <cuda_runtime.h>

// Loss_Antonymy: out = sum_i relu(1 + sign_i * tanh(||A1_i - S2_i||_2)),
// sign_i = -1 if labels[i]==2 else +1.
// N = 1048576, D = 64. Inputs: S2_out [N*64] f32, A1_out [N*64] f32, labels [N] int32.
// Output: 1 float.
//
// R5: keep unroll x4 (MLP=8 front-batched loads) but fix wave quantization:
// regs=38 -> 6 blocks/SM max, so launch exactly 148*6 = 888 blocks (1 full wave).

#define D 64

__global__ void zero_out_kernel(float* out) {
    out[0] = 0.0f;
}

__global__ __launch_bounds__(256)
void loss_antonymy_kernel(const float* __restrict__ S2,
                          const float* __restrict__ A1,
                          const int* __restrict__ labels,
                          float* __restrict__ out,
                          int nrows)
{
    const int lane  = threadIdx.x & 31;
    const int half  = lane >> 4;        // 0 or 1: which row within a pair
    const int sub   = lane & 15;        // 16 float4 = 64 floats of one row
    const int gwarp = (blockIdx.x * blockDim.x + threadIdx.x) >> 5;
    const int nwarp = (gridDim.x * blockDim.x) >> 5;
    const int ngroups = nrows >> 3;     // 8 rows per warp iteration

    float acc = 0.0f;

    for (int grp = gwarp; grp < ngroups; grp += nwarp) {
        const long long rowb = (long long)grp * 8 + half;

        // front-batch all 8 independent 16B loads (MLP=8 per thread)
        float4 av0 = __ldg(reinterpret_cast<const float4*>(A1 + (rowb + 0) * D) + sub);
        float4 sv0 = __ldg(reinterpret_cast<const float4*>(S2 + (rowb + 0) * D) + sub);
        float4 av1 = __ldg(reinterpret_cast<const float4*>(A1 + (rowb + 2) * D) + sub);
        float4 sv1 = __ldg(reinterpret_cast<const float4*>(S2 + (rowb + 2) * D) + sub);
        float4 av2 = __ldg(reinterpret_cast<const float4*>(A1 + (rowb + 4) * D) + sub);
        float4 sv2 = __ldg(reinterpret_cast<const float4*>(S2 + (rowb + 4) * D) + sub);
        float4 av3 = __ldg(reinterpret_cast<const float4*>(A1 + (rowb + 6) * D) + sub);
        float4 sv3 = __ldg(reinterpret_cast<const float4*>(S2 + (rowb + 6) * D) + sub);

        float dx, dy, dz, dw;
        dx = av0.x - sv0.x; dy = av0.y - sv0.y; dz = av0.z - sv0.z; dw = av0.w - sv0.w;
        float ss0 = dx*dx + dy*dy + dz*dz + dw*dw;
        dx = av1.x - sv1.x; dy = av1.y - sv1.y; dz = av1.z - sv1.z; dw = av1.w - sv1.w;
        float ss1 = dx*dx + dy*dy + dz*dz + dw*dw;
        dx = av2.x - sv2.x; dy = av2.y - sv2.y; dz = av2.z - sv2.z; dw = av2.w - sv2.w;
        float ss2 = dx*dx + dy*dy + dz*dz + dw*dw;
        dx = av3.x - sv3.x; dy = av3.y - sv3.y; dz = av3.z - sv3.z; dw = av3.w - sv3.w;
        float ss3 = dx*dx + dy*dy + dz*dz + dw*dw;

        // reduce each across the 16 lanes of this half-warp
        #pragma unroll
        for (int o = 8; o > 0; o >>= 1) {
            ss0 += __shfl_xor_sync(0xffffffffu, ss0, o);
            ss1 += __shfl_xor_sync(0xffffffffu, ss1, o);
            ss2 += __shfl_xor_sync(0xffffffffu, ss2, o);
            ss3 += __shfl_xor_sync(0xffffffffu, ss3, o);
        }

        if (sub == 0) {
            float sg0 = (labels[rowb + 0] == 2) ? -1.0f : 1.0f;
            float sg1 = (labels[rowb + 2] == 2) ? -1.0f : 1.0f;
            float sg2 = (labels[rowb + 4] == 2) ? -1.0f : 1.0f;
            float sg3 = (labels[rowb + 6] == 2) ? -1.0f : 1.0f;
            acc += fmaxf(0.0f, fmaf(sg0, tanhf(sqrtf(ss0)), 1.0f));
            acc += fmaxf(0.0f, fmaf(sg1, tanhf(sqrtf(ss1)), 1.0f));
            acc += fmaxf(0.0f, fmaf(sg2, tanhf(sqrtf(ss2)), 1.0f));
            acc += fmaxf(0.0f, fmaf(sg3, tanhf(sqrtf(ss3)), 1.0f));
        }
    }

    // block reduction: intra-warp, then across warps via shared, one atomic per block
    #pragma unroll
    for (int o = 16; o > 0; o >>= 1)
        acc += __shfl_xor_sync(0xffffffffu, acc, o);

    __shared__ float wsum[8];   // 256 threads -> 8 warps
    const int wid = threadIdx.x >> 5;
    if (lane == 0) wsum[wid] = acc;
    __syncthreads();

    if (wid == 0) {
        float v = (lane < (blockDim.x >> 5)) ? wsum[lane] : 0.0f;
        #pragma unroll
        for (int o = 4; o > 0; o >>= 1)
            v += __shfl_xor_sync(0xffffffffu, v, o);
        if (lane == 0)
            atomicAdd(out, v);
    }
}

extern "C" void kernel_launch(void* const* d_in, const int* in_sizes, int n_in,
                              void* d_out, int out_size)
{
    const float* S2     = (const float*)d_in[0];
    const float* A1     = (const float*)d_in[1];
    const int*   labels = (const int*)d_in[2];
    float*       out    = (float*)d_out;

    const int nrows = in_sizes[2];   // labels element count = N

    zero_out_kernel<<<1, 1>>>(out);

    // regs=38 -> 6 blocks/SM; one full wave on 148 SMs
    const int blocks = 148 * 6;
    loss_antonymy_kernel<<<blocks, 256>>>(S2, A1, labels, out, nrows);
}